// round 16
// baseline (speedup 1.0000x reference)
#include <cuda_runtime.h>
#include <cstdint>

#define DEVINL static __device__ __forceinline__

// ---------------- problem sizes ----------------
#define NB   8192      // batch (z rows)
#define ND   2048      // dim
#define NM   1024      // slices (directions)
#define NP   17        // CF points

// ---------------- GEMM config ------------------
#define CHUNKS   128               // ND / 16 k16-chunks
#define STAGE_B  16384             // per stage: A 2x4KB + B 2x4KB
#define NITER    64                // CHUNKS / 2
#define GEMM_SMEM (4 * STAGE_B)    // 64KB dynamic

// ---------------- scratch (static device, no allocs) ----------------
__device__ uint4 g_Afrag[(size_t)CHUNKS * 64 * 32];    // 4 MB
__device__ uint4 g_Bfrag[(size_t)CHUNKS * 512 * 32];   // 32 MB
__device__ float g_proj[(size_t)NM * NB];
__device__ float g_stat[NM];
__device__ int   g_done;                               // k_cf completion ticket

// ---------------- PTX helpers ----------------
DEVINL uint32_t smem_u32(const void* p) {
    uint32_t r;
    asm("{ .reg .u64 t; cvta.to.shared.u64 t, %1; cvt.u32.u64 %0, t; }" : "=r"(r) : "l"(p));
    return r;
}
DEVINL void cp16(uint32_t dst, const void* src) {
    asm volatile("cp.async.cg.shared.global [%0], [%1], 16;" :: "r"(dst), "l"(src));
}
DEVINL void cp_commit() { asm volatile("cp.async.commit_group;"); }
template <int N> DEVINL void cp_wait() { asm volatile("cp.async.wait_group %0;" :: "n"(N)); }

DEVINL uint32_t pack_bf16x2(float lo, float hi) {
    uint32_t d;
    asm("cvt.rn.bf16x2.f32 %0, %1, %2;" : "=r"(d) : "f"(hi), "f"(lo));
    return d;
}
DEVINL void lds128(uint32_t* r, uint32_t addr) {
    asm volatile("ld.shared.v4.u32 {%0,%1,%2,%3}, [%4];"
                 : "=r"(r[0]), "=r"(r[1]), "=r"(r[2]), "=r"(r[3]) : "r"(addr));
}
DEVINL void mma_bf16(float* d, const uint32_t* a, uint32_t b0, uint32_t b1) {
    asm volatile(
        "mma.sync.aligned.m16n8k16.row.col.f32.bf16.bf16.f32 "
        "{%0,%1,%2,%3}, {%4,%5,%6,%7}, {%8,%9}, {%0,%1,%2,%3};"
        : "+f"(d[0]), "+f"(d[1]), "+f"(d[2]), "+f"(d[3])
        : "r"(a[0]), "r"(a[1]), "r"(a[2]), "r"(a[3]), "r"(b0), "r"(b1));
}

// Taylor sincos for |x| <= ~0.7 (max err < 3e-7)
DEVINL void sincos_poly(float x, float* s, float* c) {
    float t = x * x;
    *c = fmaf(t, fmaf(t, fmaf(t, -1.3888889e-3f, 4.1666667e-2f), -0.5f), 1.0f);
    *s = x * fmaf(t, fmaf(t, fmaf(t, -1.9841270e-4f, 8.3333333e-3f), -1.6666667e-1f), 1.0f);
}

// ---------------- fused prep: norm + packA (blocks 0..63) | packB (blocks 64..8255) ----------------
__global__ void __launch_bounds__(256) k_prep(const float* __restrict__ z,
                                              const float* __restrict__ dirs) {
    int bid = blockIdx.x, tid = threadIdx.x;
    __shared__ uint32_t sb[8][32][4];

    if (bid < 64) {
        // ---- A side: one m16 row-group per block ----
        if (bid == 0 && tid == 0) g_done = 0;          // reset k_cf ticket
        __shared__ float s_inv[16];
        int mb = bid;
        int lane = tid & 31, w = tid >> 5;

        // norm: warp w handles rows 2w, 2w+1 (32 lanes x 16 float4 each)
#pragma unroll
        for (int h = 0; h < 2; h++) {
            int r = w * 2 + h;
            const float4* src = (const float4*)(dirs + (size_t)(mb * 16 + r) * ND);
            float ss = 0.f;
#pragma unroll
            for (int i = 0; i < 16; i++) {
                float4 v = src[lane + 32 * i];
                ss += v.x * v.x + v.y * v.y + v.z * v.z + v.w * v.w;
            }
#pragma unroll
            for (int o = 16; o; o >>= 1) ss += __shfl_down_sync(0xFFFFFFFFu, ss, o);
            if (lane == 0) s_inv[r] = 1.0f / (sqrtf(ss) + 1e-8f);
        }
        __syncthreads();

        // pack: same per-(m16, kg) logic as the standalone k_packA, looped over kg
        int r = tid >> 4;                    // row within m16 block (0..15)
        int b = tid & 15;                    // 8-k group -> chunk b/2, k-half b&1
        int row = mb * 16 + r;
        float inv = s_inv[r];
        int c = b >> 1;
        int reg = (r >> 3) + ((b & 1) << 1); // (row-half) + 2*(k-half)
        int lbase = (r & 7) * 4;
        int cc = tid >> 5, lane2 = tid & 31;

        for (int kg = 0; kg < 16; kg++) {
            const float4* src = (const float4*)(dirs + (size_t)row * ND + kg * 128 + b * 8);
            float4 v0 = src[0], v1 = src[1];
            float f[8] = {v0.x, v0.y, v0.z, v0.w, v1.x, v1.y, v1.z, v1.w};
#pragma unroll
            for (int j = 0; j < 4; j++)
                sb[c][lbase + j][reg] = pack_bf16x2(f[2 * j] * inv, f[2 * j + 1] * inv);
            __syncthreads();
            int chunk = kg * 8 + cc;
            g_Afrag[(size_t)(chunk * 64 + mb) * 32 + lane2] = ((const uint4*)sb)[tid];
            __syncthreads();                 // before sb is overwritten next kg
        }
    } else {
        // ---- B side: identical to the standalone k_packB ----
        int pb = bid - 64;
        int n16 = pb >> 4, kg = pb & 15;
        int nr = tid >> 4;                   // local n (0..15)
        int b = tid & 15;
        int nrow = n16 * 16 + nr;
        const float4* src = (const float4*)(z + (size_t)nrow * ND + kg * 128 + b * 8);
        float4 v0 = src[0], v1 = src[1];
        float f[8] = {v0.x, v0.y, v0.z, v0.w, v1.x, v1.y, v1.z, v1.w};
        int c = b >> 1;
        int comp = ((nr >> 3) << 1) + (b & 1);   // 2*(n8 half) + (k-half)
        int lbase = (nr & 7) * 4;
#pragma unroll
        for (int j = 0; j < 4; j++)
            sb[c][lbase + j][comp] = pack_bf16x2(f[2 * j], f[2 * j + 1]);
        __syncthreads();
        int cc = tid >> 5, lane = tid & 31;
        int chunk = kg * 8 + cc;
        g_Bfrag[(size_t)(chunk * 512 + n16) * 32 + lane] = ((const uint4*)sb)[tid];
    }
}

// ---------------- GEMM: proj = dirs_n @ z^T via mma.sync bf16 ----------------
// grid 512 (8 m-tiles x 64 n-tiles), 128 threads (4 warps, warp 64x64), 2 CTAs/SM.
__global__ void __launch_bounds__(128, 2) k_gemm() {
    extern __shared__ uint4 smem4[];
    uint32_t sbase = smem_u32(smem4);
    int tid = threadIdx.x;
    int lane = tid & 31, w = tid >> 5;
    int wm = w >> 1, wn = w & 1;

    int mt = blockIdx.x & 7;
    int nt = blockIdx.x >> 3;
    const uint4* Ab = g_Afrag + (size_t)mt * 8 * 32;     // + chunk*2048
    const uint4* Bb = g_Bfrag + (size_t)nt * 8 * 32;     // + chunk*16384

    float acc[4][8][4];
#pragma unroll
    for (int i = 0; i < 4; i++)
#pragma unroll
        for (int j = 0; j < 8; j++)
#pragma unroll
            for (int c = 0; c < 4; c++) acc[i][j][c] = 0.f;

    auto load_stage = [&](int s, int si) {
        int c0 = si * 2;
#pragma unroll
        for (int i = 0; i < 8; i++) {
            int lin = i * 128 + tid;
            const uint4* src;
            if (lin < 512) {
                int cl = lin >> 8, rem = lin & 255;
                src = Ab + (size_t)(c0 + cl) * 2048 + rem;
            } else {
                int l2 = lin - 512;
                int cl = l2 >> 8, rem = l2 & 255;
                src = Bb + (size_t)(c0 + cl) * 16384 + rem;
            }
            cp16(sbase + s * STAGE_B + lin * 16, src);
        }
    };

    auto load_frags = [&](uint32_t stg, int kk, uint32_t a[4][4], uint32_t bf[4][4]) {
        uint32_t As = stg + kk * 4096;
        uint32_t Bs = stg + 8192 + kk * 4096;
#pragma unroll
        for (int i = 0; i < 4; i++)
            lds128(a[i], As + (wm * 4 + i) * 512 + lane * 16);
#pragma unroll
        for (int j = 0; j < 4; j++)
            lds128(bf[j], Bs + (wn * 4 + j) * 512 + lane * 16);
    };

    auto mma_block = [&](uint32_t a[4][4], uint32_t bf[4][4]) {
#pragma unroll
        for (int i = 0; i < 4; i++)
#pragma unroll
            for (int j = 0; j < 4; j++) {
                mma_bf16(acc[i][2 * j],     a[i], bf[j][0], bf[j][1]);
                mma_bf16(acc[i][2 * j + 1], a[i], bf[j][2], bf[j][3]);
            }
    };

    load_stage(0, 0); cp_commit();
    load_stage(1, 1); cp_commit();
    load_stage(2, 2); cp_commit();
    cp_wait<1>();
    __syncthreads();

    uint32_t aC[4][4], bC[4][4], aN[4][4], bN[4][4];
    load_frags(sbase, 0, aC, bC);

    for (int it = 0; it < NITER; it++) {
        int s = it & 3;
        uint32_t stg = sbase + s * STAGE_B;
        if (it + 3 < NITER) load_stage((it + 3) & 3, it + 3);
        cp_commit();

        load_frags(stg, 1, aN, bN);      // prefetch kk=1 of this stage
        mma_block(aC, bC);               // compute kk=0
        if (it + 1 < NITER)              // prefetch kk=0 of next stage
            load_frags(sbase + ((it + 1) & 3) * STAGE_B, 0, aC, bC);
        mma_block(aN, bN);               // compute kk=1

        if (it + 1 < NITER) {
            cp_wait<1>();                // stage it+2 landed
            __syncthreads();             // visible to all; protects slot reuse
        }
    }

    int m_base = mt * 128 + wm * 64;
    int n_base = nt * 128 + wn * 64;
    int rr = lane >> 2, cc = 2 * (lane & 3);
#pragma unroll
    for (int i = 0; i < 4; i++) {
#pragma unroll
        for (int jn = 0; jn < 8; jn++) {
            int row = m_base + i * 16 + rr;
            int col = n_base + jn * 8 + cc;
            float2 lo = {acc[i][jn][0], acc[i][jn][1]};
            float2 hi = {acc[i][jn][2], acc[i][jn][3]};
            *(float2*)&g_proj[(size_t)row * NB + col]       = lo;
            *(float2*)&g_proj[(size_t)(row + 8) * NB + col] = hi;
        }
    }
}

// ---------------- fused stats + CF per slice (register-resident) ----------------
// Row data lives in v[8] registers across both passes; last block does final mean.
__global__ void __launch_bounds__(256) k_cf(float* __restrict__ out) {
    __shared__ float red[304];
    __shared__ float s_ms[2];
    int m = blockIdx.x, tid = threadIdx.x;

    const float4* pr = (const float4*)(g_proj + (size_t)m * NB);
    float4 v[8];
#pragma unroll
    for (int i = 0; i < 8; i++) v[i] = pr[tid + (i << 8)];

    float s = 0.f, ss = 0.f;
#pragma unroll
    for (int i = 0; i < 8; i++) {
        s  += v[i].x + v[i].y + v[i].z + v[i].w;
        ss += v[i].x * v[i].x + v[i].y * v[i].y + v[i].z * v[i].z + v[i].w * v[i].w;
    }
#pragma unroll
    for (int o = 16; o; o >>= 1) {
        s  += __shfl_down_sync(0xFFFFFFFFu, s, o);
        ss += __shfl_down_sync(0xFFFFFFFFu, ss, o);
    }
    if ((tid & 31) == 0) { red[tid >> 5] = s; red[8 + (tid >> 5)] = ss; }
    __syncthreads();
    if (tid == 0) {
        float S = 0.f, SS = 0.f;
#pragma unroll
        for (int w = 0; w < 8; w++) { S += red[w]; SS += red[8 + w]; }
        float mean = S / (float)NB;
        float var = (SS - (float)NB * mean * mean) / (float)(NB - 1);  // ddof=1
        var = fmaxf(var, 0.f);
        s_ms[0] = mean;
        s_ms[1] = 1.0f / (sqrtf(var) + 1e-8f);
    }
    __syncthreads();
    float mean = s_ms[0], rstd = s_ms[1];

    float aC[NP], aS[NP];
#pragma unroll
    for (int p = 0; p < NP; p++) { aC[p] = 0.f; aS[p] = 0.f; }

#pragma unroll
    for (int i = 0; i < 8; i++) {
        float xs[4] = {v[i].x, v[i].y, v[i].z, v[i].w};
#pragma unroll
        for (int u = 0; u < 4; u++) {
            float sv = (xs[u] - mean) * rstd;
            float c0, s0, cd, sd;
            sincos_poly(0.1f     * sv, &s0, &c0);  // theta_0
            sincos_poly(0.11875f * sv, &sd, &cd);  // step phi
            float k2 = cd + cd;
            float c1 = fmaf(cd, c0, -sd * s0);
            float s1 = fmaf(cd, s0,  sd * c0);
            aC[0] += c0; aS[0] += s0;
            aC[1] += c1; aS[1] += s1;
#pragma unroll
            for (int p = 2; p < NP; p++) {         // Chebyshev: 1 FMA per cos/sin
                float c2 = fmaf(k2, c1, -c0);
                float s2 = fmaf(k2, s1, -s0);
                aC[p] += c2; aS[p] += s2;
                c0 = c1; c1 = c2; s0 = s1; s1 = s2;
            }
        }
    }

    int lane = tid & 31, warp = tid >> 5;
#pragma unroll
    for (int p = 0; p < NP; p++) {
        float a = aC[p], b = aS[p];
#pragma unroll
        for (int o = 16; o; o >>= 1) {
            a += __shfl_down_sync(0xFFFFFFFFu, a, o);
            b += __shfl_down_sync(0xFFFFFFFFu, b, o);
        }
        if (lane == 0) { red[p * 8 + warp] = a; red[136 + p * 8 + warp] = b; }
    }
    __syncthreads();
    if (tid < NP) {
        float a = 0.f, b = 0.f;
#pragma unroll
        for (int w = 0; w < 8; w++) { a += red[tid * 8 + w]; b += red[136 + tid * 8 + w]; }
        float er = a * (1.0f / (float)NB);
        float ei = b * (1.0f / (float)NB);
        float t = 0.1f + 0.11875f * (float)tid;
        float g = expf(-0.5f * t * t);
        float dr = er - g;
        red[280 + tid] = dr * dr + ei * ei;
    }
    __syncthreads();
    __shared__ int s_last;
    if (tid == 0) {
        float acc2 = 0.f;
#pragma unroll
        for (int p = 0; p < NP; p++) acc2 += red[280 + p];
        g_stat[m] = acc2 * (1.0f / (float)NP);
        __threadfence();                           // g_stat visible before ticket
        s_last = (atomicAdd(&g_done, 1) == NM - 1);
    }
    __syncthreads();

    if (s_last) {                                  // last block: final mean (deterministic)
        float fs = 0.f;
#pragma unroll
        for (int i = 0; i < 4; i++) fs += g_stat[tid + (i << 8)];
#pragma unroll
        for (int o = 16; o; o >>= 1) fs += __shfl_down_sync(0xFFFFFFFFu, fs, o);
        if (lane == 0) red[warp] = fs;
        __syncthreads();
        if (tid == 0) {
            float S = 0.f;
#pragma unroll
            for (int w = 0; w < 8; w++) S += red[w];
            out[0] = S * (1.0f / (float)NM);
        }
    }
}

// ---------------- launch ----------------
extern "C" void kernel_launch(void* const* d_in, const int* in_sizes, int n_in,
                              void* d_out, int out_size) {
    const float* z    = (const float*)d_in[0];
    const float* dirs = (const float*)d_in[1];
    if (n_in >= 2 && in_sizes[0] == NM * ND && in_sizes[1] == NB * ND) {
        z = (const float*)d_in[1];      // defensive swap if metadata order flips
        dirs = (const float*)d_in[0];
    }

    cudaFuncSetAttribute(k_gemm, cudaFuncAttributeMaxDynamicSharedMemorySize, GEMM_SMEM);

    k_prep<<<64 + 512 * 16, 256>>>(z, dirs);
    k_gemm<<<512, 128, GEMM_SMEM>>>();
    k_cf<<<NM, 256>>>((float*)d_out);
}

// round 17
// speedup vs baseline: 1.0207x; 1.0207x over previous
#include <cuda_runtime.h>
#include <cstdint>

#define DEVINL static __device__ __forceinline__

// ---------------- problem sizes ----------------
#define NB   8192      // batch (z rows)
#define ND   2048      // dim
#define NM   1024      // slices (directions)
#define NP   17        // CF points

// ---------------- GEMM config ------------------
#define CHUNKS   128               // ND / 16 k16-chunks
#define STAGE_B  16384             // per stage: A 2x4KB + B 2x4KB
#define NITER    64                // CHUNKS / 2
#define GEMM_SMEM (4 * STAGE_B)    // 64KB dynamic

// ---------------- scratch (static device, no allocs) ----------------
__device__ uint4 g_Afrag[(size_t)CHUNKS * 64 * 32];    // 4 MB
__device__ uint4 g_Bfrag[(size_t)CHUNKS * 512 * 32];   // 32 MB
__device__ float g_proj[(size_t)NM * NB];
__device__ float g_stat[NM];
__device__ int   g_done;                               // k_cf completion ticket

// ---------------- PTX helpers ----------------
DEVINL uint32_t smem_u32(const void* p) {
    uint32_t r;
    asm("{ .reg .u64 t; cvta.to.shared.u64 t, %1; cvt.u32.u64 %0, t; }" : "=r"(r) : "l"(p));
    return r;
}
DEVINL void cp16(uint32_t dst, const void* src) {
    asm volatile("cp.async.cg.shared.global [%0], [%1], 16;" :: "r"(dst), "l"(src));
}
DEVINL void cp_commit() { asm volatile("cp.async.commit_group;"); }
template <int N> DEVINL void cp_wait() { asm volatile("cp.async.wait_group %0;" :: "n"(N)); }

DEVINL uint32_t pack_bf16x2(float lo, float hi) {
    uint32_t d;
    asm("cvt.rn.bf16x2.f32 %0, %1, %2;" : "=r"(d) : "f"(hi), "f"(lo));
    return d;
}
DEVINL void lds128(uint32_t* r, uint32_t addr) {
    asm volatile("ld.shared.v4.u32 {%0,%1,%2,%3}, [%4];"
                 : "=r"(r[0]), "=r"(r[1]), "=r"(r[2]), "=r"(r[3]) : "r"(addr));
}
DEVINL void mma_bf16(float* d, const uint32_t* a, uint32_t b0, uint32_t b1) {
    asm volatile(
        "mma.sync.aligned.m16n8k16.row.col.f32.bf16.bf16.f32 "
        "{%0,%1,%2,%3}, {%4,%5,%6,%7}, {%8,%9}, {%0,%1,%2,%3};"
        : "+f"(d[0]), "+f"(d[1]), "+f"(d[2]), "+f"(d[3])
        : "r"(a[0]), "r"(a[1]), "r"(a[2]), "r"(a[3]), "r"(b0), "r"(b1));
}

// Taylor sincos for |x| <= ~0.7 (max err < 3e-7)
DEVINL void sincos_poly(float x, float* s, float* c) {
    float t = x * x;
    *c = fmaf(t, fmaf(t, fmaf(t, -1.3888889e-3f, 4.1666667e-2f), -0.5f), 1.0f);
    *s = x * fmaf(t, fmaf(t, fmaf(t, -1.9841270e-4f, 8.3333333e-3f), -1.6666667e-1f), 1.0f);
}

// ---------------- fused prep: norm + packA (blocks 0..63) | packB (blocks 64..8255) ----------------
// Staging buffer padded to 33 words/row: kills the 8-way STS bank conflict
// (row stride 132 words => bank offset 4c per chunk c instead of 0).
__global__ void __launch_bounds__(256) k_prep(const float* __restrict__ z,
                                              const float* __restrict__ dirs) {
    int bid = blockIdx.x, tid = threadIdx.x;
    __shared__ __align__(16) uint32_t sb[8][33][4];   // padded: 33-word rows

    if (bid < 64) {
        // ---- A side: one m16 row-group per block ----
        if (bid == 0 && tid == 0) g_done = 0;          // reset k_cf ticket
        __shared__ float s_inv[16];
        int mb = bid;
        int lane = tid & 31, w = tid >> 5;

        // norm: warp w handles rows 2w, 2w+1
#pragma unroll
        for (int h = 0; h < 2; h++) {
            int r = w * 2 + h;
            const float4* src = (const float4*)(dirs + (size_t)(mb * 16 + r) * ND);
            float ss = 0.f;
#pragma unroll
            for (int i = 0; i < 16; i++) {
                float4 v = src[lane + 32 * i];
                ss += v.x * v.x + v.y * v.y + v.z * v.z + v.w * v.w;
            }
#pragma unroll
            for (int o = 16; o; o >>= 1) ss += __shfl_down_sync(0xFFFFFFFFu, ss, o);
            if (lane == 0) s_inv[r] = 1.0f / (sqrtf(ss) + 1e-8f);
        }
        __syncthreads();

        int r = tid >> 4;                    // row within m16 block (0..15)
        int b = tid & 15;                    // 8-k group -> chunk b/2, k-half b&1
        int row = mb * 16 + r;
        float inv = s_inv[r];
        int c = b >> 1;
        int reg = (r >> 3) + ((b & 1) << 1); // (row-half) + 2*(k-half)
        int lbase = (r & 7) * 4;
        int cc = tid >> 5, lane2 = tid & 31;

        for (int kg = 0; kg < 16; kg++) {
            const float4* src = (const float4*)(dirs + (size_t)row * ND + kg * 128 + b * 8);
            float4 v0 = src[0], v1 = src[1];
            float f[8] = {v0.x, v0.y, v0.z, v0.w, v1.x, v1.y, v1.z, v1.w};
#pragma unroll
            for (int j = 0; j < 4; j++)
                sb[c][lbase + j][reg] = pack_bf16x2(f[2 * j] * inv, f[2 * j + 1] * inv);
            __syncthreads();
            int chunk = kg * 8 + cc;
            g_Afrag[(size_t)(chunk * 64 + mb) * 32 + lane2] =
                *(const uint4*)&sb[cc][lane2][0];
            __syncthreads();                 // before sb is overwritten next kg
        }
    } else {
        // ---- B side ----
        int pb = bid - 64;
        int n16 = pb >> 4, kg = pb & 15;
        int nr = tid >> 4;                   // local n (0..15)
        int b = tid & 15;
        int nrow = n16 * 16 + nr;
        const float4* src = (const float4*)(z + (size_t)nrow * ND + kg * 128 + b * 8);
        float4 v0 = src[0], v1 = src[1];
        float f[8] = {v0.x, v0.y, v0.z, v0.w, v1.x, v1.y, v1.z, v1.w};
        int c = b >> 1;
        int comp = ((nr >> 3) << 1) + (b & 1);   // 2*(n8 half) + (k-half)
        int lbase = (nr & 7) * 4;
#pragma unroll
        for (int j = 0; j < 4; j++)
            sb[c][lbase + j][comp] = pack_bf16x2(f[2 * j], f[2 * j + 1]);
        __syncthreads();
        int cc = tid >> 5, lane = tid & 31;
        int chunk = kg * 8 + cc;
        g_Bfrag[(size_t)(chunk * 512 + n16) * 32 + lane] =
            *(const uint4*)&sb[cc][lane][0];
    }
}

// ---------------- GEMM: proj = dirs_n @ z^T via mma.sync bf16 ----------------
// grid 512 (8 m-tiles x 64 n-tiles), 128 threads (4 warps, warp 64x64), 2 CTAs/SM.
__global__ void __launch_bounds__(128, 2) k_gemm() {
    extern __shared__ uint4 smem4[];
    uint32_t sbase = smem_u32(smem4);
    int tid = threadIdx.x;
    int lane = tid & 31, w = tid >> 5;
    int wm = w >> 1, wn = w & 1;

    int mt = blockIdx.x & 7;
    int nt = blockIdx.x >> 3;
    const uint4* Ab = g_Afrag + (size_t)mt * 8 * 32;     // + chunk*2048
    const uint4* Bb = g_Bfrag + (size_t)nt * 8 * 32;     // + chunk*16384

    float acc[4][8][4];
#pragma unroll
    for (int i = 0; i < 4; i++)
#pragma unroll
        for (int j = 0; j < 8; j++)
#pragma unroll
            for (int c = 0; c < 4; c++) acc[i][j][c] = 0.f;

    auto load_stage = [&](int s, int si) {
        int c0 = si * 2;
#pragma unroll
        for (int i = 0; i < 8; i++) {
            int lin = i * 128 + tid;
            const uint4* src;
            if (lin < 512) {
                int cl = lin >> 8, rem = lin & 255;
                src = Ab + (size_t)(c0 + cl) * 2048 + rem;
            } else {
                int l2 = lin - 512;
                int cl = l2 >> 8, rem = l2 & 255;
                src = Bb + (size_t)(c0 + cl) * 16384 + rem;
            }
            cp16(sbase + s * STAGE_B + lin * 16, src);
        }
    };

    auto load_frags = [&](uint32_t stg, int kk, uint32_t a[4][4], uint32_t bf[4][4]) {
        uint32_t As = stg + kk * 4096;
        uint32_t Bs = stg + 8192 + kk * 4096;
#pragma unroll
        for (int i = 0; i < 4; i++)
            lds128(a[i], As + (wm * 4 + i) * 512 + lane * 16);
#pragma unroll
        for (int j = 0; j < 4; j++)
            lds128(bf[j], Bs + (wn * 4 + j) * 512 + lane * 16);
    };

    auto mma_block = [&](uint32_t a[4][4], uint32_t bf[4][4]) {
#pragma unroll
        for (int i = 0; i < 4; i++)
#pragma unroll
            for (int j = 0; j < 4; j++) {
                mma_bf16(acc[i][2 * j],     a[i], bf[j][0], bf[j][1]);
                mma_bf16(acc[i][2 * j + 1], a[i], bf[j][2], bf[j][3]);
            }
    };

    load_stage(0, 0); cp_commit();
    load_stage(1, 1); cp_commit();
    load_stage(2, 2); cp_commit();
    cp_wait<1>();
    __syncthreads();

    uint32_t aC[4][4], bC[4][4], aN[4][4], bN[4][4];
    load_frags(sbase, 0, aC, bC);

    for (int it = 0; it < NITER; it++) {
        int s = it & 3;
        uint32_t stg = sbase + s * STAGE_B;
        if (it + 3 < NITER) load_stage((it + 3) & 3, it + 3);
        cp_commit();

        load_frags(stg, 1, aN, bN);      // prefetch kk=1 of this stage
        mma_block(aC, bC);               // compute kk=0
        if (it + 1 < NITER)              // prefetch kk=0 of next stage
            load_frags(sbase + ((it + 1) & 3) * STAGE_B, 0, aC, bC);
        mma_block(aN, bN);               // compute kk=1

        if (it + 1 < NITER) {
            cp_wait<1>();                // stage it+2 landed
            __syncthreads();             // visible to all; protects slot reuse
        }
    }

    int m_base = mt * 128 + wm * 64;
    int n_base = nt * 128 + wn * 64;
    int rr = lane >> 2, cc = 2 * (lane & 3);
#pragma unroll
    for (int i = 0; i < 4; i++) {
#pragma unroll
        for (int jn = 0; jn < 8; jn++) {
            int row = m_base + i * 16 + rr;
            int col = n_base + jn * 8 + cc;
            float2 lo = {acc[i][jn][0], acc[i][jn][1]};
            float2 hi = {acc[i][jn][2], acc[i][jn][3]};
            *(float2*)&g_proj[(size_t)row * NB + col]       = lo;
            *(float2*)&g_proj[(size_t)(row + 8) * NB + col] = hi;
        }
    }
}

// ---------------- fused stats + CF per slice (register-resident) ----------------
__global__ void __launch_bounds__(256) k_cf(float* __restrict__ out) {
    __shared__ float red[304];
    __shared__ float s_ms[2];
    int m = blockIdx.x, tid = threadIdx.x;

    const float4* pr = (const float4*)(g_proj + (size_t)m * NB);
    float4 v[8];
#pragma unroll
    for (int i = 0; i < 8; i++) v[i] = pr[tid + (i << 8)];

    float s = 0.f, ss = 0.f;
#pragma unroll
    for (int i = 0; i < 8; i++) {
        s  += v[i].x + v[i].y + v[i].z + v[i].w;
        ss += v[i].x * v[i].x + v[i].y * v[i].y + v[i].z * v[i].z + v[i].w * v[i].w;
    }
#pragma unroll
    for (int o = 16; o; o >>= 1) {
        s  += __shfl_down_sync(0xFFFFFFFFu, s, o);
        ss += __shfl_down_sync(0xFFFFFFFFu, ss, o);
    }
    if ((tid & 31) == 0) { red[tid >> 5] = s; red[8 + (tid >> 5)] = ss; }
    __syncthreads();
    if (tid == 0) {
        float S = 0.f, SS = 0.f;
#pragma unroll
        for (int w = 0; w < 8; w++) { S += red[w]; SS += red[8 + w]; }
        float mean = S / (float)NB;
        float var = (SS - (float)NB * mean * mean) / (float)(NB - 1);  // ddof=1
        var = fmaxf(var, 0.f);
        s_ms[0] = mean;
        s_ms[1] = 1.0f / (sqrtf(var) + 1e-8f);
    }
    __syncthreads();
    float mean = s_ms[0], rstd = s_ms[1];

    float aC[NP], aS[NP];
#pragma unroll
    for (int p = 0; p < NP; p++) { aC[p] = 0.f; aS[p] = 0.f; }

#pragma unroll
    for (int i = 0; i < 8; i++) {
        float xs[4] = {v[i].x, v[i].y, v[i].z, v[i].w};
#pragma unroll
        for (int u = 0; u < 4; u++) {
            float sv = (xs[u] - mean) * rstd;
            float c0, s0, cd, sd;
            sincos_poly(0.1f     * sv, &s0, &c0);  // theta_0
            sincos_poly(0.11875f * sv, &sd, &cd);  // step phi
            float k2 = cd + cd;
            float c1 = fmaf(cd, c0, -sd * s0);
            float s1 = fmaf(cd, s0,  sd * c0);
            aC[0] += c0; aS[0] += s0;
            aC[1] += c1; aS[1] += s1;
#pragma unroll
            for (int p = 2; p < NP; p++) {         // Chebyshev: 1 FMA per cos/sin
                float c2 = fmaf(k2, c1, -c0);
                float s2 = fmaf(k2, s1, -s0);
                aC[p] += c2; aS[p] += s2;
                c0 = c1; c1 = c2; s0 = s1; s1 = s2;
            }
        }
    }

    int lane = tid & 31, warp = tid >> 5;
#pragma unroll
    for (int p = 0; p < NP; p++) {
        float a = aC[p], b = aS[p];
#pragma unroll
        for (int o = 16; o; o >>= 1) {
            a += __shfl_down_sync(0xFFFFFFFFu, a, o);
            b += __shfl_down_sync(0xFFFFFFFFu, b, o);
        }
        if (lane == 0) { red[p * 8 + warp] = a; red[136 + p * 8 + warp] = b; }
    }
    __syncthreads();
    if (tid < NP) {
        float a = 0.f, b = 0.f;
#pragma unroll
        for (int w = 0; w < 8; w++) { a += red[tid * 8 + w]; b += red[136 + tid * 8 + w]; }
        float er = a * (1.0f / (float)NB);
        float ei = b * (1.0f / (float)NB);
        float t = 0.1f + 0.11875f * (float)tid;
        float g = expf(-0.5f * t * t);
        float dr = er - g;
        red[280 + tid] = dr * dr + ei * ei;
    }
    __syncthreads();
    __shared__ int s_last;
    if (tid == 0) {
        float acc2 = 0.f;
#pragma unroll
        for (int p = 0; p < NP; p++) acc2 += red[280 + p];
        g_stat[m] = acc2 * (1.0f / (float)NP);
        __threadfence();                           // g_stat visible before ticket
        s_last = (atomicAdd(&g_done, 1) == NM - 1);
    }
    __syncthreads();

    if (s_last) {                                  // last block: final mean (deterministic)
        float fs = 0.f;
#pragma unroll
        for (int i = 0; i < 4; i++) fs += g_stat[tid + (i << 8)];
#pragma unroll
        for (int o = 16; o; o >>= 1) fs += __shfl_down_sync(0xFFFFFFFFu, fs, o);
        if (lane == 0) red[warp] = fs;
        __syncthreads();
        if (tid == 0) {
            float S = 0.f;
#pragma unroll
            for (int w = 0; w < 8; w++) S += red[w];
            out[0] = S * (1.0f / (float)NM);
        }
    }
}

// ---------------- launch ----------------
extern "C" void kernel_launch(void* const* d_in, const int* in_sizes, int n_in,
                              void* d_out, int out_size) {
    const float* z    = (const float*)d_in[0];
    const float* dirs = (const float*)d_in[1];
    if (n_in >= 2 && in_sizes[0] == NM * ND && in_sizes[1] == NB * ND) {
        z = (const float*)d_in[1];      // defensive swap if metadata order flips
        dirs = (const float*)d_in[0];
    }

    cudaFuncSetAttribute(k_gemm, cudaFuncAttributeMaxDynamicSharedMemorySize, GEMM_SMEM);

    k_prep<<<64 + 512 * 16, 256>>>(z, dirs);
    k_gemm<<<512, 128, GEMM_SMEM>>>();
    k_cf<<<NM, 256>>>((float*)d_out);
}